// round 5
// baseline (speedup 1.0000x reference)
#include <cuda_runtime.h>

// Problem constants
#define Bv   16
#define Cv   2
#define Tv   2000
#define Fv   257
#define NCH  40          // number of time chunks
#define Lc   50          // chunk length (NCH*Lc == Tv)
#define BF   (Bv*Fv)     // 4112 independent scan chains

// Scratch (no cudaMalloc allowed): chunk-end partials and carry-ins.
__device__ float g_e[NCH * BF];
__device__ float g_carry[NCH * BF];

__device__ __forceinline__ float sigmoidf(float x) {
    return 1.0f / (1.0f + expf(-x));
}
__device__ __forceinline__ float sqrt_approx(float x) {
    float r;
    asm("sqrt.approx.f32 %0, %1;" : "=f"(r) : "f"(x));
    return r;
}

// K1: chunk-local EMA partial scan on channel 0 ONLY (zero init state, record
// chunk-end value). ch0 is the only streaming L2 traffic in this kernel, so it
// stays L2-resident (65.8 MB < 126 MB) for K3's re-read without explicit hints.
__global__ void __launch_bounds__(128) k1_partial(
        const float* __restrict__ in,
        const float* __restrict__ alpha_p) {
    int id = blockIdx.x * blockDim.x + threadIdx.x;
    if (id >= Bv * NCH * Fv) return;
    int f  = id % Fv;
    int bc = id / Fv;
    int ch = bc % NCH;
    int b  = bc / NCH;

    float alpha = sigmoidf(alpha_p[f]);
    const float2* x0 = (const float2*)in
        + ((size_t)(b * Cv + 0) * Tv + (size_t)ch * Lc) * Fv + f;

    float s = 0.0f;
#pragma unroll 10
    for (int t = 0; t < Lc; ++t) {
        float2 v = __ldg(&x0[(size_t)t * Fv]);
        float m = fmaf(v.x, v.x, v.y * v.y);
        s = fmaf(alpha, m - s, s);          // s = s*(1-a) + m*a
    }
    g_e[ch * BF + b * Fv + f] = s;
}

// K2: sequential combine over NCH chunks per chain: carry[k] = state before chunk k.
__global__ void k2_combine(const float* __restrict__ s1,
                           const float* __restrict__ alpha_p) {
    int id = blockIdx.x * blockDim.x + threadIdx.x;  // id = b*Fv + f
    if (id >= BF) return;
    int f = id % Fv;
    float alpha = sigmoidf(alpha_p[f]);
    float aL = powf(1.0f - alpha, (float)Lc);
    float s = s1[id];                                // s_1[b,0,f,0]
#pragma unroll
    for (int k = 0; k < NCH; ++k) {
        g_carry[k * BF + id] = s;
        s = fmaf(aL, s, g_e[k * BF + id]);           // state after chunk k
    }
}

// K3 (fused): re-scan each chunk with correct carry-in (ch0 now L2-resident),
// emit smooth + res ch0 + s_final, PLUS the independent ch1 elementwise norm.
__global__ void __launch_bounds__(128) k3_final(
        const float* __restrict__ in,
        const float* __restrict__ alpha_p,
        const float* __restrict__ w,
        const float* __restrict__ bi,
        float* __restrict__ res,
        float* __restrict__ sfin,
        float* __restrict__ smooth) {
    int id = blockIdx.x * blockDim.x + threadIdx.x;
    if (id >= Bv * NCH * Fv) return;
    int f  = id % Fv;
    int bc = id / Fv;
    int ch = bc % NCH;
    int b  = bc / NCH;

    float alpha = sigmoidf(alpha_p[f]);
    float w0 = w[f];
    float b0 = bi[f];
    float w1 = w[Fv + f];
    float b1 = bi[Fv + f];
    float s = g_carry[ch * BF + b * Fv + f];

    size_t base0 = ((size_t)(b * Cv + 0) * Tv + (size_t)ch * Lc) * Fv + f;
    size_t base1 = ((size_t)(b * Cv + 1) * Tv + (size_t)ch * Lc) * Fv + f;
    const float2* x0 = (const float2*)in + base0;
    const float2* x1 = (const float2*)in + base1;
    float2* r0 = (float2*)res + base0;
    float2* r1 = (float2*)res + base1;
    float* sm = smooth ? smooth + ((size_t)b * Tv + (size_t)ch * Lc) * Fv + f : (float*)0;

#pragma unroll 5
    for (int t = 0; t < Lc; ++t) {
        // ch0: L2-resident from K1; last use -> evict_first streaming load
        float2 v0 = __ldcs(&x0[(size_t)t * Fv]);
        float m = fmaf(v0.x, v0.x, v0.y * v0.y);
        s = fmaf(alpha, m - s, s);
        float sd = sqrt_approx(s);
        float inv0 = __fdividef(w0, sd + 1e-8f);
        float2 o0;
        o0.x = fmaf(v0.x, inv0, b0);
        o0.y = fmaf(v0.y, inv0, b0);
        __stcs(&r0[(size_t)t * Fv], o0);
        if (sm) __stcs(&sm[(size_t)t * Fv], sd);

        // ch1: pure streaming elementwise
        float2 v1 = __ldcs(&x1[(size_t)t * Fv]);
        float mag = sqrt_approx(fmaf(v1.x, v1.x, v1.y * v1.y));
        float inv1 = __fdividef(w1, mag + 1e-8f);
        float2 o1;
        o1.x = fmaf(v1.x, inv1, b1);
        o1.y = fmaf(v1.y, inv1, b1);
        __stcs(&r1[(size_t)t * Fv], o1);
    }
    if (ch == NCH - 1 && sfin) sfin[b * Fv + f] = s;   // s_final == last smooth state
}

extern "C" void kernel_launch(void* const* d_in, const int* in_sizes, int n_in,
                              void* d_out, int out_size) {
    const float* in  = (const float*)d_in[0];   // [B,C,T,F,2]
    const float* s1  = (const float*)d_in[1];   // [B,1,F,1]
    const float* w   = (const float*)d_in[2];   // [1,C,1,F,1]
    const float* bi  = (const float*)d_in[3];   // [1,C,1,F,1]
    const float* ap  = (const float*)d_in[4];   // [1,1,F,1]

    float* out = (float*)d_out;
    const long long RESN = (long long)Bv * Cv * Tv * Fv * 2;  // 32,896,000
    const long long SFN  = (long long)BF;                     // 4,112
    const long long SMN  = (long long)Bv * Tv * Fv;           // 8,224,000

    float* res    = out;
    float* sfin   = (float*)0;
    float* smooth = (float*)0;
    long long osz = (long long)out_size;
    if (osz >= RESN + SFN + SMN) {            // (res, s_final, smooth_data) concatenated
        sfin   = out + RESN;
        smooth = out + RESN + SFN;
    } else if (osz >= RESN + SMN) {           // (res, smooth_data)
        smooth = out + RESN;
    }

    const int BLK = 128;
    int n1 = Bv * NCH * Fv;                   // 164,480
    k1_partial<<<(n1 + BLK - 1) / BLK, BLK>>>(in, ap);
    k2_combine<<<(BF + 255) / 256, 256>>>(s1, ap);
    k3_final  <<<(n1 + BLK - 1) / BLK, BLK>>>(in, ap, w, bi, res, sfin, smooth);
}